// round 1
// baseline (speedup 1.0000x reference)
#include <cuda_runtime.h>
#include <cuda_bf16.h>
#include <math.h>

// Problem dims
#define T_ 160
#define B_ 256
#define H_ 256
#define G_ 1024   // 4H
#define K_ 512    // Cin for both layers (C=512, 2H=512)
#define NCTA_REC 128

// ---------------- scratch (device globals; no runtime alloc allowed) --------
__device__ float g_xgf[(size_t)T_ * G_ * B_];   // [T,4H,B] forward dir
__device__ float g_xgb[(size_t)T_ * G_ * B_];   // [T,4H,B] backward dir
__device__ float g_h0 [(size_t)T_ * B_ * 512];  // layer-0 output [T,B,2H]
__device__ float g_hst[2][2][H_][B_];           // double-buffered h state [buf][dir][k][b]
__device__ unsigned g_count = 0;
__device__ volatile unsigned g_gen = 0;

// ---------------- grid barrier (all CTAs co-resident) -----------------------
__device__ __forceinline__ void grid_barrier(unsigned nb) {
    __syncthreads();
    if (threadIdx.x == 0) {
        unsigned gen = g_gen;               // volatile read
        __threadfence();
        if (atomicAdd(&g_count, 1) == nb - 1) {
            g_count = 0;
            __threadfence();
            g_gen = gen + 1;                // release
        } else {
            while (g_gen == gen) { }        // spin (volatile)
        }
        __threadfence();
    }
    __syncthreads();
}

// ---------------- input GEMM: xg = x @ Wih^T + (bih+bhh), both dirs ---------
// Output layout [T, 4H, B]. Grid: (btile=2, jtile=16 (8/dir), t=160), 256 thr.
__global__ __launch_bounds__(256) void gemm_xg(
    const float* __restrict__ X_ext,   // [T*B, 512] (layer0 x) or unused
    int use_h0,                        // layer1: read g_h0 instead
    const float* __restrict__ Wf, const float* __restrict__ Wb,   // [1024,512]
    const float* __restrict__ bif, const float* __restrict__ bhf,
    const float* __restrict__ bib, const float* __restrict__ bhb)
{
    const float* X = use_h0 ? g_h0 : X_ext;

    int t  = blockIdx.z;
    int jt = blockIdx.y;            // 0..15
    int bt = blockIdx.x;            // 0..1
    int dir = jt >> 3;
    int j0  = (jt & 7) * 128;
    int b0  = bt * 128;
    const float* W  = dir ? Wb  : Wf;
    const float* bi = dir ? bib : bif;
    const float* bh = dir ? bhb : bhf;
    float* out = dir ? g_xgb : g_xgf;

    __shared__ float Ash[32][132];
    __shared__ float Bsh[32][132];

    int tid = threadIdx.x;
    int ty = tid >> 4, tx = tid & 15;

    float acc[8][8];
    #pragma unroll
    for (int i = 0; i < 8; i++)
        #pragma unroll
        for (int j = 0; j < 8; j++) acc[i][j] = 0.f;

    const float* Xbase = X + ((size_t)t * B_ + b0) * K_;
    const float* Wbase = W + (size_t)j0 * K_;

    for (int k0 = 0; k0 < K_; k0 += 32) {
        #pragma unroll
        for (int i = 0; i < 4; i++) {
            int f4  = tid + i * 256;        // 0..1023
            int row = f4 >> 3;              // 0..127
            int c4  = (f4 & 7) * 4;         // 0..28
            float4 v = *(const float4*)(Wbase + (size_t)row * K_ + k0 + c4);
            Ash[c4+0][row] = v.x; Ash[c4+1][row] = v.y;
            Ash[c4+2][row] = v.z; Ash[c4+3][row] = v.w;
            float4 u = *(const float4*)(Xbase + (size_t)row * K_ + k0 + c4);
            Bsh[c4+0][row] = u.x; Bsh[c4+1][row] = u.y;
            Bsh[c4+2][row] = u.z; Bsh[c4+3][row] = u.w;
        }
        __syncthreads();
        #pragma unroll
        for (int k = 0; k < 32; k++) {
            float af[8], bf[8];
            #pragma unroll
            for (int i = 0; i < 4; i++) {
                float4 a4 = *(const float4*)&Ash[k][ty*8 + i*4];
                af[i*4+0]=a4.x; af[i*4+1]=a4.y; af[i*4+2]=a4.z; af[i*4+3]=a4.w;
                float4 b4 = *(const float4*)&Bsh[k][tx*8 + i*4];
                bf[i*4+0]=b4.x; bf[i*4+1]=b4.y; bf[i*4+2]=b4.z; bf[i*4+3]=b4.w;
            }
            #pragma unroll
            for (int i = 0; i < 8; i++)
                #pragma unroll
                for (int j = 0; j < 8; j++)
                    acc[i][j] += af[i] * bf[j];
        }
        __syncthreads();
    }

    #pragma unroll
    for (int i = 0; i < 8; i++) {
        int j = j0 + ty*8 + i;
        float bsum = bi[j] + bh[j];
        float* orow = out + ((size_t)t * G_ + j) * B_ + b0 + tx*8;
        #pragma unroll
        for (int jj = 0; jj < 8; jj++) orow[jj] = acc[i][jj] + bsum;
    }
}

// ---------------- persistent recurrence (both dirs, grid-synced) ------------
// 128 CTAs: dir = bid>>6, each CTA owns 4 hidden units (16 gate rows in smem).
// thread = batch element.
__global__ void __launch_bounds__(256, 1) lstm_rec(
    const float* __restrict__ Whhf, const float* __restrict__ Whhb, // [1024,256]
    float* __restrict__ out_ext, int to_ext)
{
    float* out = to_ext ? out_ext : g_h0;   // [T,B,512]
    int bid = blockIdx.x;
    int dir = bid >> 6;
    int m   = bid & 63;
    int h0i = m * 4;
    int tid = threadIdx.x;                  // batch index b
    const float* Whh = dir ? Whhb : Whhf;
    const float* xg  = dir ? g_xgb : g_xgf;

    __shared__ float wsh[16][256];          // rows: r = q*4+jj -> gate row q*256+h0i+jj
    for (int i = tid; i < 16 * 64; i += 256) {
        int r  = i >> 6;
        int c4 = (i & 63) * 4;
        int grow = (r >> 2) * H_ + h0i + (r & 3);
        *(float4*)&wsh[r][c4] = *(const float4*)(Whh + (size_t)grow * H_ + c4);
    }
    // zero read-buffer 0 (both dirs)
    {
        float* hz = &g_hst[0][0][0][0];
        for (int i = bid * 256 + tid; i < 2 * H_ * B_; i += NCTA_REC * 256) hz[i] = 0.f;
    }
    grid_barrier(NCTA_REC);

    float c[4] = {0.f, 0.f, 0.f, 0.f};

    for (int step = 0; step < T_; step++) {
        int t  = dir ? (T_ - 1 - step) : step;
        int rb = step & 1;
        const float* hp = &g_hst[rb][dir][0][0];

        float acc[16];
        #pragma unroll
        for (int r = 0; r < 16; r++) acc[r] = 0.f;

        #pragma unroll 2
        for (int k4 = 0; k4 < H_; k4 += 4) {
            float hv0 = __ldcg(hp + (k4+0) * B_ + tid);
            float hv1 = __ldcg(hp + (k4+1) * B_ + tid);
            float hv2 = __ldcg(hp + (k4+2) * B_ + tid);
            float hv3 = __ldcg(hp + (k4+3) * B_ + tid);
            #pragma unroll
            for (int r = 0; r < 16; r++) {
                float4 w = *(const float4*)&wsh[r][k4];
                acc[r] += w.x * hv0;
                acc[r] += w.y * hv1;
                acc[r] += w.z * hv2;
                acc[r] += w.w * hv3;
            }
        }

        const float* xgt = xg + (size_t)t * (G_ * B_);
        #pragma unroll
        for (int jj = 0; jj < 4; jj++) {
            int h = h0i + jj;
            float gi = acc[0*4+jj] + xgt[(0*H_ + h) * B_ + tid];
            float gf = acc[1*4+jj] + xgt[(1*H_ + h) * B_ + tid];
            float gg = acc[2*4+jj] + xgt[(2*H_ + h) * B_ + tid];
            float go = acc[3*4+jj] + xgt[(3*H_ + h) * B_ + tid];
            float iv = 1.f / (1.f + expf(-gi));
            float fv = 1.f / (1.f + expf(-gf));
            float gv = tanhf(gg);
            float ov = 1.f / (1.f + expf(-go));
            c[jj] = fv * c[jj] + iv * gv;
            float hval = ov * tanhf(c[jj]);
            __stcg(&g_hst[rb ^ 1][dir][h][tid], hval);
            out[((size_t)t * B_ + tid) * 512 + dir * H_ + h] = hval;
        }
        grid_barrier(NCTA_REC);
    }
}

// ---------------- launch --------------------------------------------------
extern "C" void kernel_launch(void* const* d_in, const int* in_sizes, int n_in,
                              void* d_out, int out_size) {
    const float* x     = (const float*)d_in[0];
    const float* wih0f = (const float*)d_in[1];
    const float* whh0f = (const float*)d_in[2];
    const float* bih0f = (const float*)d_in[3];
    const float* bhh0f = (const float*)d_in[4];
    const float* wih0b = (const float*)d_in[5];
    const float* whh0b = (const float*)d_in[6];
    const float* bih0b = (const float*)d_in[7];
    const float* bhh0b = (const float*)d_in[8];
    const float* wih1f = (const float*)d_in[9];
    const float* whh1f = (const float*)d_in[10];
    const float* bih1f = (const float*)d_in[11];
    const float* bhh1f = (const float*)d_in[12];
    const float* wih1b = (const float*)d_in[13];
    const float* whh1b = (const float*)d_in[14];
    const float* bih1b = (const float*)d_in[15];
    const float* bhh1b = (const float*)d_in[16];
    float* out = (float*)d_out;

    dim3 gg(2, 16, T_);
    // layer 0
    gemm_xg<<<gg, 256>>>(x, 0, wih0f, wih0b, bih0f, bhh0f, bih0b, bhh0b);
    lstm_rec<<<NCTA_REC, 256>>>(whh0f, whh0b, out, 0);
    // layer 1 (input = g_h0)
    gemm_xg<<<gg, 256>>>(nullptr, 1, wih1f, wih1b, bih1f, bhh1f, bih1b, bhh1b);
    lstm_rec<<<NCTA_REC, 256>>>(whh1f, whh1b, out, 1);
}

// round 2
// speedup vs baseline: 1.1733x; 1.1733x over previous
#include <cuda_runtime.h>
#include <cuda_bf16.h>
#include <math.h>
#include <stdint.h>

// Problem dims
#define T_ 160
#define B_ 256
#define H_ 256
#define G_ 1024   // 4H
#define K_ 512    // Cin for both layers (C=512, 2H=512)
#define NCTA_REC 128

// ---------------- scratch (device globals; no runtime alloc allowed) --------
__device__ float g_xgf[(size_t)T_ * G_ * B_];   // [T,4H,B] forward dir
__device__ float g_xgb[(size_t)T_ * G_ * B_];   // [T,4H,B] backward dir
__device__ float g_h0 [(size_t)T_ * B_ * 512];  // layer-0 output [T,B,2H]
__device__ float g_hst[2][2][H_][B_];           // double-buffered h state
__device__ unsigned g_count = 0;
__device__ volatile unsigned g_gen = 0;

// ---------------- helpers ---------------------------------------------------
__device__ __forceinline__ uint32_t f2tf32(float f) {
    uint32_t r;
    asm("cvt.rna.tf32.f32 %0, %1;" : "=r"(r) : "f"(f));
    return r;
}

__device__ __forceinline__ void mma_tf32(float c[4], const uint32_t a[4], const uint32_t b[2]) {
    asm volatile(
        "mma.sync.aligned.m16n8k8.row.col.f32.tf32.tf32.f32 "
        "{%0,%1,%2,%3}, {%4,%5,%6,%7}, {%8,%9}, {%0,%1,%2,%3};"
        : "+f"(c[0]), "+f"(c[1]), "+f"(c[2]), "+f"(c[3])
        : "r"(a[0]), "r"(a[1]), "r"(a[2]), "r"(a[3]), "r"(b[0]), "r"(b[1]));
}

// ---------------- grid barrier (all CTAs co-resident) -----------------------
__device__ __forceinline__ void grid_barrier(unsigned nb) {
    __syncthreads();
    if (threadIdx.x == 0) {
        unsigned gen = g_gen;
        __threadfence();
        if (atomicAdd(&g_count, 1) == nb - 1) {
            g_count = 0;
            __threadfence();
            g_gen = gen + 1;
        } else {
            while (g_gen == gen) { }
        }
        __threadfence();
    }
    __syncthreads();
}

// ---------------- input GEMM (tf32 tensor cores) ----------------------------
// xg[t, j, b] = sum_k W[j,k] * X[t*B+b, k] + (bih[j]+bhh[j])
// Output layout [T, 4H, B]. Grid: (btile=2, jtile=16 (8/dir), t=160), 256 thr.
// CTA tile 128(j) x 128(b), 8 warps as 2(m) x 4(n); warp tile 64 x 32.
#define AS_STR 36    // ≡ 4 (mod 32)  -> conflict-free A fragment loads
#define BS_STR 132   // ≡ 4 (mod 32)  -> conflict-free B fragment loads

__global__ __launch_bounds__(256, 2) void gemm_xg(
    const float* __restrict__ X_ext, int use_h0,
    const float* __restrict__ Wf, const float* __restrict__ Wb,
    const float* __restrict__ bif, const float* __restrict__ bhf,
    const float* __restrict__ bib, const float* __restrict__ bhb)
{
    const float* X = use_h0 ? g_h0 : X_ext;

    int t  = blockIdx.z;
    int jt = blockIdx.y;            // 0..15
    int bt = blockIdx.x;            // 0..1
    int dir = jt >> 3;
    int j0  = (jt & 7) * 128;
    int b0  = bt * 128;
    const float* W  = dir ? Wb  : Wf;
    const float* bi = dir ? bib : bif;
    const float* bh = dir ? bhb : bhf;
    float* out = dir ? g_xgb : g_xgf;

    __shared__ __align__(16) uint32_t As[128][AS_STR];  // [m][k]  (tf32)
    __shared__ __align__(16) uint32_t Bs[32][BS_STR];   // [k][b]  (tf32)

    int tid  = threadIdx.x;
    int wid  = tid >> 5;
    int lane = tid & 31;
    int gid  = lane >> 2;           // 0..7
    int tig  = lane & 3;            // 0..3
    int wm   = wid >> 2;            // 0..1  -> m offset 64*wm
    int wn   = wid & 3;             // 0..3  -> n offset 32*wn
    int m_base = wm * 64;
    int n_base = wn * 32;

    float acc[4][4][4];
    #pragma unroll
    for (int mi = 0; mi < 4; mi++)
        #pragma unroll
        for (int ni = 0; ni < 4; ni++)
            #pragma unroll
            for (int r = 0; r < 4; r++) acc[mi][ni][r] = 0.f;

    const float* Xbase = X + ((size_t)t * B_ + b0) * K_;
    const float* Wbase = W + (size_t)j0 * K_;

    for (int k0 = 0; k0 < K_; k0 += 32) {
        // cooperative copy: A 128x32 (direct), B 32x128 (transposed), tf32-rounded
        #pragma unroll
        for (int i = 0; i < 4; i++) {
            int f4  = tid + i * 256;        // 0..1023
            int row = f4 >> 3;              // 0..127
            int c4  = (f4 & 7) * 4;         // 0..28
            float4 v = *(const float4*)(Wbase + (size_t)row * K_ + k0 + c4);
            uint4 tv;
            tv.x = f2tf32(v.x); tv.y = f2tf32(v.y);
            tv.z = f2tf32(v.z); tv.w = f2tf32(v.w);
            *(uint4*)&As[row][c4] = tv;
            float4 u = *(const float4*)(Xbase + (size_t)row * K_ + k0 + c4);
            Bs[c4+0][row] = f2tf32(u.x);
            Bs[c4+1][row] = f2tf32(u.y);
            Bs[c4+2][row] = f2tf32(u.z);
            Bs[c4+3][row] = f2tf32(u.w);
        }
        __syncthreads();

        #pragma unroll
        for (int sub = 0; sub < 4; sub++) {     // 4 x k8
            int ks = sub * 8;
            uint32_t a[4][4];
            #pragma unroll
            for (int mi = 0; mi < 4; mi++) {
                const uint32_t* ap = &As[m_base + mi*16 + gid][ks + tig];
                a[mi][0] = ap[0];
                a[mi][1] = ap[8 * AS_STR];
                a[mi][2] = ap[4];
                a[mi][3] = ap[8 * AS_STR + 4];
            }
            uint32_t b[4][2];
            #pragma unroll
            for (int ni = 0; ni < 4; ni++) {
                const uint32_t* bp = &Bs[ks + tig][n_base + ni*8 + gid];
                b[ni][0] = bp[0];
                b[ni][1] = bp[4 * BS_STR];
            }
            #pragma unroll
            for (int mi = 0; mi < 4; mi++)
                #pragma unroll
                for (int ni = 0; ni < 4; ni++)
                    mma_tf32(acc[mi][ni], a[mi], b[ni]);
        }
        __syncthreads();
    }

    // epilogue: bias + store (float2 per fragment row)
    #pragma unroll
    for (int mi = 0; mi < 4; mi++) {
        int j_lo = j0 + m_base + mi*16 + gid;
        int j_hi = j_lo + 8;
        float bs_lo = bi[j_lo] + bh[j_lo];
        float bs_hi = bi[j_hi] + bh[j_hi];
        #pragma unroll
        for (int ni = 0; ni < 4; ni++) {
            int bc = b0 + n_base + ni*8 + 2*tig;
            float2 lo = make_float2(acc[mi][ni][0] + bs_lo, acc[mi][ni][1] + bs_lo);
            float2 hi = make_float2(acc[mi][ni][2] + bs_hi, acc[mi][ni][3] + bs_hi);
            *(float2*)(out + ((size_t)t * G_ + j_lo) * B_ + bc) = lo;
            *(float2*)(out + ((size_t)t * G_ + j_hi) * B_ + bc) = hi;
        }
    }
}

// ---------------- persistent recurrence (both dirs, grid-synced) ------------
__global__ void __launch_bounds__(256, 1) lstm_rec(
    const float* __restrict__ Whhf, const float* __restrict__ Whhb,
    float* __restrict__ out_ext, int to_ext)
{
    float* out = to_ext ? out_ext : g_h0;   // [T,B,512]
    int bid = blockIdx.x;
    int dir = bid >> 6;
    int m   = bid & 63;
    int h0i = m * 4;
    int tid = threadIdx.x;                  // batch index b
    const float* Whh = dir ? Whhb : Whhf;
    const float* xg  = dir ? g_xgb : g_xgf;

    __shared__ float wsh[16][256];
    for (int i = tid; i < 16 * 64; i += 256) {
        int r  = i >> 6;
        int c4 = (i & 63) * 4;
        int grow = (r >> 2) * H_ + h0i + (r & 3);
        *(float4*)&wsh[r][c4] = *(const float4*)(Whh + (size_t)grow * H_ + c4);
    }
    {
        float* hz = &g_hst[0][0][0][0];
        for (int i = bid * 256 + tid; i < 2 * H_ * B_; i += NCTA_REC * 256) hz[i] = 0.f;
    }
    grid_barrier(NCTA_REC);

    float c[4] = {0.f, 0.f, 0.f, 0.f};

    for (int step = 0; step < T_; step++) {
        int t  = dir ? (T_ - 1 - step) : step;
        int rb = step & 1;
        const float* hp = &g_hst[rb][dir][0][0];

        float acc[16];
        #pragma unroll
        for (int r = 0; r < 16; r++) acc[r] = 0.f;

        #pragma unroll 2
        for (int k4 = 0; k4 < H_; k4 += 4) {
            float hv0 = __ldcg(hp + (k4+0) * B_ + tid);
            float hv1 = __ldcg(hp + (k4+1) * B_ + tid);
            float hv2 = __ldcg(hp + (k4+2) * B_ + tid);
            float hv3 = __ldcg(hp + (k4+3) * B_ + tid);
            #pragma unroll
            for (int r = 0; r < 16; r++) {
                float4 w = *(const float4*)&wsh[r][k4];
                acc[r] += w.x * hv0;
                acc[r] += w.y * hv1;
                acc[r] += w.z * hv2;
                acc[r] += w.w * hv3;
            }
        }

        const float* xgt = xg + (size_t)t * (G_ * B_);
        #pragma unroll
        for (int jj = 0; jj < 4; jj++) {
            int h = h0i + jj;
            float gi = acc[0*4+jj] + xgt[(0*H_ + h) * B_ + tid];
            float gf = acc[1*4+jj] + xgt[(1*H_ + h) * B_ + tid];
            float gg = acc[2*4+jj] + xgt[(2*H_ + h) * B_ + tid];
            float go = acc[3*4+jj] + xgt[(3*H_ + h) * B_ + tid];
            float iv = 1.f / (1.f + expf(-gi));
            float fv = 1.f / (1.f + expf(-gf));
            float gv = tanhf(gg);
            float ov = 1.f / (1.f + expf(-go));
            c[jj] = fv * c[jj] + iv * gv;
            float hval = ov * tanhf(c[jj]);
            __stcg(&g_hst[rb ^ 1][dir][h][tid], hval);
            out[((size_t)t * B_ + tid) * 512 + dir * H_ + h] = hval;
        }
        grid_barrier(NCTA_REC);
    }
}

// ---------------- launch --------------------------------------------------
extern "C" void kernel_launch(void* const* d_in, const int* in_sizes, int n_in,
                              void* d_out, int out_size) {
    const float* x     = (const float*)d_in[0];
    const float* wih0f = (const float*)d_in[1];
    const float* whh0f = (const float*)d_in[2];
    const float* bih0f = (const float*)d_in[3];
    const float* bhh0f = (const float*)d_in[4];
    const float* wih0b = (const float*)d_in[5];
    const float* whh0b = (const float*)d_in[6];
    const float* bih0b = (const float*)d_in[7];
    const float* bhh0b = (const float*)d_in[8];
    const float* wih1f = (const float*)d_in[9];
    const float* whh1f = (const float*)d_in[10];
    const float* bih1f = (const float*)d_in[11];
    const float* bhh1f = (const float*)d_in[12];
    const float* wih1b = (const float*)d_in[13];
    const float* whh1b = (const float*)d_in[14];
    const float* bih1b = (const float*)d_in[15];
    const float* bhh1b = (const float*)d_in[16];
    float* out = (float*)d_out;

    dim3 gg(2, 16, T_);
    // layer 0
    gemm_xg<<<gg, 256>>>(x, 0, wih0f, wih0b, bih0f, bhh0f, bih0b, bhh0b);
    lstm_rec<<<NCTA_REC, 256>>>(whh0f, whh0b, out, 0);
    // layer 1 (input = g_h0)
    gemm_xg<<<gg, 256>>>(nullptr, 1, wih1f, wih1b, bih1f, bhh1f, bih1b, bhh1b);
    lstm_rec<<<NCTA_REC, 256>>>(whh1f, whh1b, out, 1);
}

// round 3
// speedup vs baseline: 1.9562x; 1.6672x over previous
#include <cuda_runtime.h>
#include <cuda_bf16.h>
#include <math.h>
#include <stdint.h>

// Problem dims
#define T_ 160
#define B_ 256
#define H_ 256
#define G_ 1024   // 4H
#define K_ 512    // Cin for both layers (C=512, 2H=512)

// ---------------- scratch (device globals; no runtime alloc allowed) --------
__device__ float g_xgf[(size_t)T_ * G_ * B_];   // [T,4H,B] forward dir
__device__ float g_xgb[(size_t)T_ * G_ * B_];   // [T,4H,B] backward dir
__device__ float g_h0 [(size_t)T_ * B_ * 512];  // layer-0 output [T,B,2H]
__device__ float g_hst[2][2][H_][B_];           // double-buffered h state [buf][dir][k][b]
__device__ unsigned g_rcnt[8][32];              // per-group barrier counters (padded lines)
__device__ volatile unsigned g_rgen[8][32];

// ---------------- helpers ---------------------------------------------------
__device__ __forceinline__ uint32_t f2tf32(float f) {
    uint32_t r;
    asm("cvt.rna.tf32.f32 %0, %1;" : "=r"(r) : "f"(f));
    return r;
}

__device__ __forceinline__ void mma_tf32(float c[4], const uint32_t a[4], const uint32_t b[2]) {
    asm volatile(
        "mma.sync.aligned.m16n8k8.row.col.f32.tf32.tf32.f32 "
        "{%0,%1,%2,%3}, {%4,%5,%6,%7}, {%8,%9}, {%0,%1,%2,%3};"
        : "+f"(c[0]), "+f"(c[1]), "+f"(c[2]), "+f"(c[3])
        : "r"(a[0]), "r"(a[1]), "r"(a[2]), "r"(a[3]), "r"(b[0]), "r"(b[1]));
}

// 16-CTA group barrier (CTAs sharing dir+batch-tile)
__device__ __forceinline__ void group_barrier(int grp) {
    __syncthreads();
    if (threadIdx.x == 0) {
        unsigned gen = g_rgen[grp][0];
        __threadfence();
        if (atomicAdd(&g_rcnt[grp][0], 1) == 15) {
            g_rcnt[grp][0] = 0;
            __threadfence();
            g_rgen[grp][0] = gen + 1;
        } else {
            while (g_rgen[grp][0] == gen) { }
        }
        __threadfence();
    }
    __syncthreads();
}

// ---------------- input GEMM (tf32 tensor cores) ----------------------------
#define AS_STR 36
#define BS_STR 132

__global__ __launch_bounds__(256, 2) void gemm_xg(
    const float* __restrict__ X_ext, int use_h0,
    const float* __restrict__ Wf, const float* __restrict__ Wb,
    const float* __restrict__ bif, const float* __restrict__ bhf,
    const float* __restrict__ bib, const float* __restrict__ bhb)
{
    const float* X = use_h0 ? g_h0 : X_ext;

    int t  = blockIdx.z;
    int jt = blockIdx.y;
    int bt = blockIdx.x;
    int dir = jt >> 3;
    int j0  = (jt & 7) * 128;
    int b0  = bt * 128;
    const float* W  = dir ? Wb  : Wf;
    const float* bi = dir ? bib : bif;
    const float* bh = dir ? bhb : bhf;
    float* out = dir ? g_xgb : g_xgf;

    __shared__ __align__(16) uint32_t As[128][AS_STR];
    __shared__ __align__(16) uint32_t Bs[32][BS_STR];

    int tid  = threadIdx.x;
    int wid  = tid >> 5;
    int lane = tid & 31;
    int gid  = lane >> 2;
    int tig  = lane & 3;
    int wm   = wid >> 2;
    int wn   = wid & 3;
    int m_base = wm * 64;
    int n_base = wn * 32;

    float acc[4][4][4];
    #pragma unroll
    for (int mi = 0; mi < 4; mi++)
        #pragma unroll
        for (int ni = 0; ni < 4; ni++)
            #pragma unroll
            for (int r = 0; r < 4; r++) acc[mi][ni][r] = 0.f;

    const float* Xbase = X + ((size_t)t * B_ + b0) * K_;
    const float* Wbase = W + (size_t)j0 * K_;

    for (int k0 = 0; k0 < K_; k0 += 32) {
        #pragma unroll
        for (int i = 0; i < 4; i++) {
            int f4  = tid + i * 256;
            int row = f4 >> 3;
            int c4  = (f4 & 7) * 4;
            float4 v = *(const float4*)(Wbase + (size_t)row * K_ + k0 + c4);
            uint4 tv;
            tv.x = f2tf32(v.x); tv.y = f2tf32(v.y);
            tv.z = f2tf32(v.z); tv.w = f2tf32(v.w);
            *(uint4*)&As[row][c4] = tv;
            float4 u = *(const float4*)(Xbase + (size_t)row * K_ + k0 + c4);
            Bs[c4+0][row] = f2tf32(u.x);
            Bs[c4+1][row] = f2tf32(u.y);
            Bs[c4+2][row] = f2tf32(u.z);
            Bs[c4+3][row] = f2tf32(u.w);
        }
        __syncthreads();

        #pragma unroll
        for (int sub = 0; sub < 4; sub++) {
            int ks = sub * 8;
            uint32_t a[4][4];
            #pragma unroll
            for (int mi = 0; mi < 4; mi++) {
                const uint32_t* ap = &As[m_base + mi*16 + gid][ks + tig];
                a[mi][0] = ap[0];
                a[mi][1] = ap[8 * AS_STR];
                a[mi][2] = ap[4];
                a[mi][3] = ap[8 * AS_STR + 4];
            }
            uint32_t b[4][2];
            #pragma unroll
            for (int ni = 0; ni < 4; ni++) {
                const uint32_t* bp = &Bs[ks + tig][n_base + ni*8 + gid];
                b[ni][0] = bp[0];
                b[ni][1] = bp[4 * BS_STR];
            }
            #pragma unroll
            for (int mi = 0; mi < 4; mi++)
                #pragma unroll
                for (int ni = 0; ni < 4; ni++)
                    mma_tf32(acc[mi][ni], a[mi], b[ni]);
        }
        __syncthreads();
    }

    #pragma unroll
    for (int mi = 0; mi < 4; mi++) {
        int j_lo = j0 + m_base + mi*16 + gid;
        int j_hi = j_lo + 8;
        float bs_lo = bi[j_lo] + bh[j_lo];
        float bs_hi = bi[j_hi] + bh[j_hi];
        #pragma unroll
        for (int ni = 0; ni < 4; ni++) {
            int bc = b0 + n_base + ni*8 + 2*tig;
            float2 lo = make_float2(acc[mi][ni][0] + bs_lo, acc[mi][ni][1] + bs_lo);
            float2 hi = make_float2(acc[mi][ni][2] + bs_hi, acc[mi][ni][3] + bs_hi);
            *(float2*)(out + ((size_t)t * G_ + j_lo) * B_ + bc) = lo;
            *(float2*)(out + ((size_t)t * G_ + j_hi) * B_ + bc) = hi;
        }
    }
}

// ---------------- recurrence: tf32 MMA, persistent, group-synced ------------
// 128 CTAs: dir = bid>>6, ug = (bid>>2)&15 (16 hidden units), bt = bid&3 (64 batch).
// Smem: W[64][260] tf32, Hhi[256][72] tf32, Hlo[256][72] tf32 (acc aliases Hlo).
#define W_STR 260
#define H_STR 72
#define REC_BS 64
#define REC_SMEM ((64*W_STR + 2*256*H_STR) * 4)

__global__ void __launch_bounds__(256, 1) lstm_rec_mma(
    const float* __restrict__ Whhf, const float* __restrict__ Whhb,
    float* __restrict__ out_ext, int to_ext)
{
    extern __shared__ uint32_t sm[];
    uint32_t* Wsh = sm;                       // [64][W_STR]
    uint32_t* Hhi = sm + 64*W_STR;            // [256][H_STR]
    uint32_t* Hlo = Hhi + 256*H_STR;          // [256][H_STR]
    float*    Acc = (float*)Hlo;              // [64][H_STR] alias (post-MMA)

    float* out = to_ext ? out_ext : g_h0;
    int bid = blockIdx.x;
    int dir = bid >> 6;
    int ug  = (bid >> 2) & 15;
    int bt  = bid & 3;
    int b0  = bt * REC_BS;
    int grp = dir * 4 + bt;
    int tid = threadIdx.x;
    const float* Whh = dir ? Whhb : Whhf;
    const float* xg  = dir ? g_xgb : g_xgf;

    // preload W tile (rows r = g*16+u -> Whh[g*H + ug*16+u]), tf32
    for (int i = tid; i < 64 * 64; i += 256) {
        int r  = i >> 6;
        int c4 = (i & 63) * 4;
        int grow = (r >> 4) * H_ + ug * 16 + (r & 15);
        float4 v = *(const float4*)(Whh + (size_t)grow * H_ + c4);
        uint32_t* dst = Wsh + r * W_STR + c4;
        dst[0] = f2tf32(v.x); dst[1] = f2tf32(v.y);
        dst[2] = f2tf32(v.z); dst[3] = f2tf32(v.w);
    }
    // zero own slice of h read-buffer 0: k in [ug*16,+16), b in [b0,+64)
    {
        int k = ug * 16 + (tid >> 4);
        int b = b0 + (tid & 15) * 4;
        *(float4*)&g_hst[0][dir][k][b] = make_float4(0.f, 0.f, 0.f, 0.f);
    }
    group_barrier(grp);

    int wid  = tid >> 5;
    int lane = tid & 31;
    int gid  = lane >> 2;
    int tig  = lane & 3;
    int m0   = (wid >> 1) * 16;
    int n0   = (wid & 1) * 32;
    int pb   = tid >> 2;          // pointwise: batch (local)
    int pu4  = (tid & 3) * 4;     // pointwise: unit base (4 consecutive)

    float cst[4] = {0.f, 0.f, 0.f, 0.f};

    for (int step = 0; step < T_; step++) {
        int t = dir ? (T_ - 1 - step) : step;
        const float* hp = &g_hst[step & 1][dir][0][b0];

        // stage h tile [256 k][64 b] -> tf32 hi + lo
        #pragma unroll 4
        for (int i = tid; i < 256 * 16; i += 256) {
            int k  = i >> 4;
            int cc = (i & 15) * 4;
            float4 v = *(const float4*)(hp + (size_t)k * B_ + cc);
            uint4 vh, vl;
            vh.x = f2tf32(v.x); vl.x = f2tf32(v.x - __uint_as_float(vh.x));
            vh.y = f2tf32(v.y); vl.y = f2tf32(v.y - __uint_as_float(vh.y));
            vh.z = f2tf32(v.z); vl.z = f2tf32(v.z - __uint_as_float(vh.z));
            vh.w = f2tf32(v.w); vl.w = f2tf32(v.w - __uint_as_float(vh.w));
            *(uint4*)(Hhi + k * H_STR + cc) = vh;
            *(uint4*)(Hlo + k * H_STR + cc) = vl;
        }
        __syncthreads();

        float acc[4][4];
        #pragma unroll
        for (int f = 0; f < 4; f++)
            #pragma unroll
            for (int r = 0; r < 4; r++) acc[f][r] = 0.f;

        #pragma unroll 4
        for (int k8 = 0; k8 < 32; k8++) {
            int ks = k8 * 8;
            uint32_t a[4];
            const uint32_t* ap = Wsh + (m0 + gid) * W_STR + ks + tig;
            a[0] = ap[0];
            a[1] = ap[8 * W_STR];
            a[2] = ap[4];
            a[3] = ap[8 * W_STR + 4];
            #pragma unroll
            for (int f = 0; f < 4; f++) {
                const uint32_t* bph = Hhi + (ks + tig) * H_STR + n0 + f*8 + gid;
                uint32_t bh[2] = { bph[0], bph[4 * H_STR] };
                mma_tf32(acc[f], a, bh);
                const uint32_t* bpl = Hlo + (ks + tig) * H_STR + n0 + f*8 + gid;
                uint32_t bl[2] = { bpl[0], bpl[4 * H_STR] };
                mma_tf32(acc[f], a, bl);
            }
        }
        __syncthreads();   // all MMA reads of Hlo done -> safe to alias as Acc

        #pragma unroll
        for (int f = 0; f < 4; f++) {
            int col = n0 + f*8 + 2*tig;
            *(float2*)&Acc[(m0 + gid    ) * H_STR + col] = make_float2(acc[f][0], acc[f][1]);
            *(float2*)&Acc[(m0 + gid + 8) * H_STR + col] = make_float2(acc[f][2], acc[f][3]);
        }
        __syncthreads();

        // pointwise: thread owns (b = pb, units pu4..pu4+3)
        const float* xgt = xg + (size_t)t * (G_ * B_) + b0;
        int bgl = b0 + pb;
        float hv[4];
        #pragma unroll
        for (int j = 0; j < 4; j++) {
            int u = pu4 + j;
            float gi = Acc[( 0 + u) * H_STR + pb] + xgt[(0*H_ + ug*16 + u) * B_ + pb];
            float gf = Acc[(16 + u) * H_STR + pb] + xgt[(1*H_ + ug*16 + u) * B_ + pb];
            float gg = Acc[(32 + u) * H_STR + pb] + xgt[(2*H_ + ug*16 + u) * B_ + pb];
            float go = Acc[(48 + u) * H_STR + pb] + xgt[(3*H_ + ug*16 + u) * B_ + pb];
            float iv = 1.f / (1.f + expf(-gi));
            float fv = 1.f / (1.f + expf(-gf));
            float gv = tanhf(gg);
            float ov = 1.f / (1.f + expf(-go));
            cst[j] = fv * cst[j] + iv * gv;
            hv[j] = ov * tanhf(cst[j]);
            g_hst[(step & 1) ^ 1][dir][ug*16 + u][bgl] = hv[j];
        }
        *(float4*)(out + ((size_t)t * B_ + bgl) * 512 + dir * H_ + ug*16 + pu4) =
            make_float4(hv[0], hv[1], hv[2], hv[3]);

        group_barrier(grp);
    }
}

// ---------------- launch --------------------------------------------------
extern "C" void kernel_launch(void* const* d_in, const int* in_sizes, int n_in,
                              void* d_out, int out_size) {
    const float* x     = (const float*)d_in[0];
    const float* wih0f = (const float*)d_in[1];
    const float* whh0f = (const float*)d_in[2];
    const float* bih0f = (const float*)d_in[3];
    const float* bhh0f = (const float*)d_in[4];
    const float* wih0b = (const float*)d_in[5];
    const float* whh0b = (const float*)d_in[6];
    const float* bih0b = (const float*)d_in[7];
    const float* bhh0b = (const float*)d_in[8];
    const float* wih1f = (const float*)d_in[9];
    const float* whh1f = (const float*)d_in[10];
    const float* bih1f = (const float*)d_in[11];
    const float* bhh1f = (const float*)d_in[12];
    const float* wih1b = (const float*)d_in[13];
    const float* whh1b = (const float*)d_in[14];
    const float* bih1b = (const float*)d_in[15];
    const float* bhh1b = (const float*)d_in[16];
    float* out = (float*)d_out;

    cudaFuncSetAttribute(lstm_rec_mma, cudaFuncAttributeMaxDynamicSharedMemorySize, REC_SMEM);

    dim3 gg(2, 16, T_);
    // layer 0
    gemm_xg<<<gg, 256>>>(x, 0, wih0f, wih0b, bih0f, bhh0f, bih0b, bhh0b);
    lstm_rec_mma<<<128, 256, REC_SMEM>>>(whh0f, whh0b, out, 0);
    // layer 1 (input = g_h0)
    gemm_xg<<<gg, 256>>>(nullptr, 1, wih1f, wih1b, bih1f, bhh1f, bih1b, bhh1b);
    lstm_rec_mma<<<128, 256, REC_SMEM>>>(whh1f, whh1b, out, 1);
}

// round 4
// speedup vs baseline: 3.4388x; 1.7579x over previous
#include <cuda_runtime.h>
#include <math.h>
#include <stdint.h>

// Problem dims
#define T_ 160
#define B_ 256
#define H_ 256
#define G_ 1024   // 4H
#define K_ 512    // Cin for both layers

// ---------------- scratch (device globals) ----------------------------------
__device__ float g_xr [(size_t)T_ * B_ * K_];     // x, tf32-rounded
__device__ float g_wr [4][(size_t)G_ * K_];       // Wih l0f,l0b,l1f,l1b rounded
__device__ float g_xgf[(size_t)T_ * G_ * B_];     // [T,4H,B] fwd
__device__ float g_xgb[(size_t)T_ * G_ * B_];     // [T,4H,B] bwd
__device__ float g_h0 [(size_t)T_ * B_ * 512];    // layer-0 out (pre-rounded)
__device__ float g_hst[2][2][B_][H_];             // h state [buf][dir][b][k]
__device__ unsigned g_rcnt[8][32];
__device__ volatile unsigned g_rgen[8][32];

// ---------------- helpers ---------------------------------------------------
__device__ __forceinline__ uint32_t f2tf32(float f) {
    uint32_t r;
    asm("cvt.rna.tf32.f32 %0, %1;" : "=r"(r) : "f"(f));
    return r;
}
__device__ __forceinline__ void mma_tf32(float c[4], const uint32_t a[4], const uint32_t b[2]) {
    asm volatile(
        "mma.sync.aligned.m16n8k8.row.col.f32.tf32.tf32.f32 "
        "{%0,%1,%2,%3}, {%4,%5,%6,%7}, {%8,%9}, {%0,%1,%2,%3};"
        : "+f"(c[0]), "+f"(c[1]), "+f"(c[2]), "+f"(c[3])
        : "r"(a[0]), "r"(a[1]), "r"(a[2]), "r"(a[3]), "r"(b[0]), "r"(b[1]));
}
__device__ __forceinline__ uint32_t cvta_s(const void* p) {
    return (uint32_t)__cvta_generic_to_shared(p);
}
__device__ __forceinline__ void cp16(uint32_t s, const void* g) {
    asm volatile("cp.async.cg.shared.global [%0], [%1], 16;\n" :: "r"(s), "l"(g));
}
#define CP_COMMIT() asm volatile("cp.async.commit_group;\n")
#define CP_WAIT0()  asm volatile("cp.async.wait_group 0;\n")
#define CP_WAIT1()  asm volatile("cp.async.wait_group 1;\n")

__device__ __forceinline__ float sigm_f(float x) {
    return __fdividef(1.f, 1.f + __expf(-x));
}
__device__ __forceinline__ float tanh_f(float x) {
    float e = __expf(2.f * x);
    return (e - 1.f) * __fdividef(1.f, e + 1.f);
}

// 16-CTA group barrier (CTAs sharing dir+batch-tile)
__device__ __forceinline__ void group_barrier(int grp) {
    __syncthreads();
    if (threadIdx.x == 0) {
        unsigned gen = g_rgen[grp][0];
        __threadfence();
        if (atomicAdd(&g_rcnt[grp][0], 1) == 15) {
            g_rcnt[grp][0] = 0;
            __threadfence();
            g_rgen[grp][0] = gen + 1;
        } else {
            while (g_rgen[grp][0] == gen) { }
        }
        __threadfence();
    }
    __syncthreads();
}

// ---------------- prep: tf32-round x and the four Wih -----------------------
__global__ void prep_round(const float* __restrict__ x,
                           const float* __restrict__ w0f, const float* __restrict__ w0b,
                           const float* __restrict__ w1f, const float* __restrict__ w1b)
{
    size_t i = (size_t)blockIdx.x * blockDim.x + threadIdx.x;
    size_t stride = (size_t)gridDim.x * blockDim.x;
    const size_t NX = (size_t)T_ * B_ * K_ / 4;
    const size_t NW = (size_t)G_ * K_ / 4;
    for (size_t c = i; c < NX; c += stride) {
        float4 v = ((const float4*)x)[c];
        v.x = __uint_as_float(f2tf32(v.x)); v.y = __uint_as_float(f2tf32(v.y));
        v.z = __uint_as_float(f2tf32(v.z)); v.w = __uint_as_float(f2tf32(v.w));
        ((float4*)g_xr)[c] = v;
    }
    const float* ws[4] = { w0f, w0b, w1f, w1b };
    #pragma unroll
    for (int l = 0; l < 4; l++) {
        for (size_t c = i; c < NW; c += stride) {
            float4 v = ((const float4*)ws[l])[c];
            v.x = __uint_as_float(f2tf32(v.x)); v.y = __uint_as_float(f2tf32(v.y));
            v.z = __uint_as_float(f2tf32(v.z)); v.w = __uint_as_float(f2tf32(v.w));
            ((float4*)g_wr[l])[c] = v;
        }
    }
}

// ---------------- input GEMM: tf32 MMA + cp.async double buffer -------------
// xg[t,j,b] = sum_k W[j,k]*X[t*B+b,k] + bias. Tiles [m=128 j][k] & [n=128 b][k].
#define GS 36
#define GEMM_SMEM (2 * 2 * 128 * GS * 4)   // 2 stages x (A+B) x 128 x GS floats

__global__ __launch_bounds__(256, 2) void gemm_xg(
    int layer,
    const float* __restrict__ bif, const float* __restrict__ bhf,
    const float* __restrict__ bib, const float* __restrict__ bhb)
{
    extern __shared__ float gsm[];
    const float* X = layer ? g_h0 : g_xr;

    int t  = blockIdx.z;
    int jt = blockIdx.y;
    int bt = blockIdx.x;
    int dir = jt >> 3;
    int j0  = (jt & 7) * 128;
    int b0  = bt * 128;
    const float* W  = g_wr[layer * 2 + dir];
    const float* bi = dir ? bib : bif;
    const float* bh = dir ? bhb : bhf;
    float* out = dir ? g_xgb : g_xgf;

    int tid  = threadIdx.x;
    int wid  = tid >> 5;
    int lane = tid & 31;
    int gid  = lane >> 2;
    int tig  = lane & 3;
    int m_base = (wid >> 2) * 64;
    int n_base = (wid & 3) * 32;

    const float* Xb = X + ((size_t)t * B_ + b0) * K_;
    const float* Wb = W + (size_t)j0 * K_;

    float acc[4][4][4];
    #pragma unroll
    for (int mi = 0; mi < 4; mi++)
        #pragma unroll
        for (int ni = 0; ni < 4; ni++)
            #pragma unroll
            for (int r = 0; r < 4; r++) acc[mi][ni][r] = 0.f;

    int row0 = tid >> 3;          // 0..31 step covers 128 rows over 4 iters
    int cx0  = (tid & 7) * 4;

    // prologue: stage 0
    {
        float* As = gsm;
        float* Bs = gsm + 128 * GS;
        #pragma unroll
        for (int i = 0; i < 4; i++) {
            int row = row0 + i * 32;
            cp16(cvta_s(As + row * GS + cx0), Wb + (size_t)row * K_ + cx0);
            cp16(cvta_s(Bs + row * GS + cx0), Xb + (size_t)row * K_ + cx0);
        }
        CP_COMMIT();
    }

    for (int s = 0; s < 16; s++) {
        if (s < 15) {
            int k0 = (s + 1) * 32;
            float* As = gsm + ((s + 1) & 1) * (2 * 128 * GS);
            float* Bs = As + 128 * GS;
            #pragma unroll
            for (int i = 0; i < 4; i++) {
                int row = row0 + i * 32;
                cp16(cvta_s(As + row * GS + cx0), Wb + (size_t)row * K_ + k0 + cx0);
                cp16(cvta_s(Bs + row * GS + cx0), Xb + (size_t)row * K_ + k0 + cx0);
            }
            CP_COMMIT();
            CP_WAIT1();
        } else {
            CP_WAIT0();
        }
        __syncthreads();

        const float* As = gsm + (s & 1) * (2 * 128 * GS);
        const float* Bs = As + 128 * GS;

        #pragma unroll
        for (int sub = 0; sub < 4; sub++) {
            int ks = sub * 8;
            uint32_t a[4][4];
            #pragma unroll
            for (int mi = 0; mi < 4; mi++) {
                const float* ap = As + (m_base + mi * 16 + gid) * GS + ks + tig;
                a[mi][0] = __float_as_uint(ap[0]);
                a[mi][1] = __float_as_uint(ap[8 * GS]);
                a[mi][2] = __float_as_uint(ap[4]);
                a[mi][3] = __float_as_uint(ap[8 * GS + 4]);
            }
            uint32_t b[4][2];
            #pragma unroll
            for (int ni = 0; ni < 4; ni++) {
                const float* bp = Bs + (n_base + ni * 8 + gid) * GS + ks + tig;
                b[ni][0] = __float_as_uint(bp[0]);
                b[ni][1] = __float_as_uint(bp[4]);
            }
            #pragma unroll
            for (int mi = 0; mi < 4; mi++)
                #pragma unroll
                for (int ni = 0; ni < 4; ni++)
                    mma_tf32(acc[mi][ni], a[mi], b[ni]);
        }
        __syncthreads();
    }

    #pragma unroll
    for (int mi = 0; mi < 4; mi++) {
        int j_lo = j0 + m_base + mi * 16 + gid;
        int j_hi = j_lo + 8;
        float bs_lo = bi[j_lo] + bh[j_lo];
        float bs_hi = bi[j_hi] + bh[j_hi];
        #pragma unroll
        for (int ni = 0; ni < 4; ni++) {
            int bc = b0 + n_base + ni * 8 + 2 * tig;
            float2 lo = make_float2(acc[mi][ni][0] + bs_lo, acc[mi][ni][1] + bs_lo);
            float2 hi = make_float2(acc[mi][ni][2] + bs_hi, acc[mi][ni][3] + bs_hi);
            *(float2*)(out + ((size_t)t * G_ + j_lo) * B_ + bc) = lo;
            *(float2*)(out + ((size_t)t * G_ + j_hi) * B_ + bc) = hi;
        }
    }
}

// ---------------- recurrence: tf32 MMA, W in regs, cp.async staging ---------
// 128 CTAs: dir=bid>>6, ug=(bid>>2)&15 (16 units), bt=bid&3 (64 batch).
#define HS 260
#define REC_SMEM ((64 * HS + 64 * 64) * 4)

__global__ void __launch_bounds__(256, 1) lstm_rec_mma(
    const float* __restrict__ Whhf, const float* __restrict__ Whhb,
    float* __restrict__ out_ext, int to_ext)
{
    extern __shared__ float sm[];
    float* Hs  = sm;                 // [64 b][HS] (k contiguous)
    float* XGs = sm + 64 * HS;       // [64 gate-row][64 b]
    float* Acc = Hs;                 // alias after MMA

    float* out = to_ext ? out_ext : g_h0;
    int bid = blockIdx.x;
    int dir = bid >> 6;
    int ug  = (bid >> 2) & 15;
    int bt  = bid & 3;
    int b0  = bt * 64;
    int grp = dir * 4 + bt;
    int tid = threadIdx.x;
    int wid = tid >> 5, lane = tid & 31, gid = lane >> 2, tig = lane & 3;
    int m0 = (wid >> 1) * 16;
    int n0 = (wid & 1) * 32;
    const float* Whh = dir ? Whhb : Whhf;
    const float* xg  = dir ? g_xgb : g_xgf;

    // W fragments -> registers (rna-rounded once)
    uint32_t A0[32], A1[32], A2[32], A3[32];
    {
        int rl = m0 + gid, rh = rl + 8;
        const float* wl = Whh + (size_t)((rl >> 4) * H_ + ug * 16 + (rl & 15)) * H_;
        const float* wh = Whh + (size_t)((rh >> 4) * H_ + ug * 16 + (rh & 15)) * H_;
        #pragma unroll
        for (int k8 = 0; k8 < 32; k8++) {
            A0[k8] = f2tf32(wl[k8 * 8 + tig]);
            A1[k8] = f2tf32(wh[k8 * 8 + tig]);
            A2[k8] = f2tf32(wl[k8 * 8 + tig + 4]);
            A3[k8] = f2tf32(wh[k8 * 8 + tig + 4]);
        }
    }
    // zero own slice of h buffer 0
    {
        int b = b0 + (tid >> 2);
        int k = ug * 16 + (tid & 3) * 4;
        *(float4*)&g_hst[0][dir][b][k] = make_float4(0.f, 0.f, 0.f, 0.f);
    }
    int pb  = tid & 63;
    int pu4 = (tid >> 6) * 4;

    // prefetch xg for step 0
    {
        int t0 = dir ? T_ - 1 : 0;
        const float* xgt = xg + (size_t)t0 * (G_ * B_);
        #pragma unroll
        for (int i = 0; i < 4; i++) {
            int c = tid + i * 256;
            int r = c >> 4, boff = (c & 15) * 4;
            int grow = (r >> 4) * H_ + ug * 16 + (r & 15);
            cp16(cvta_s(XGs + r * 64 + boff), xgt + (size_t)grow * B_ + b0 + boff);
        }
        CP_COMMIT();
    }
    group_barrier(grp);

    float cst[4] = {0.f, 0.f, 0.f, 0.f};

    for (int step = 0; step < T_; step++) {
        int t = dir ? (T_ - 1 - step) : step;

        // stage h tile [64 b][256 k] via cp.async (L2)
        #pragma unroll
        for (int i = 0; i < 16; i++) {
            int c = tid + i * 256;
            int b = c >> 6, koff = (c & 63) * 4;
            cp16(cvta_s(Hs + b * HS + koff), &g_hst[step & 1][dir][b0 + b][koff]);
        }
        CP_COMMIT();
        CP_WAIT0();     // waits Hs AND the xg prefetch
        __syncthreads();

        float acc[4][4];
        #pragma unroll
        for (int f = 0; f < 4; f++)
            #pragma unroll
            for (int r = 0; r < 4; r++) acc[f][r] = 0.f;

        const float* bbase = Hs + (size_t)(n0 + gid) * HS + tig;
        #pragma unroll
        for (int k8 = 0; k8 < 32; k8++) {
            uint32_t a[4] = { A0[k8], A1[k8], A2[k8], A3[k8] };
            #pragma unroll
            for (int f = 0; f < 4; f++) {
                const float* bp = bbase + f * 8 * HS + k8 * 8;
                uint32_t b2[2] = { __float_as_uint(bp[0]), __float_as_uint(bp[4]) };
                mma_tf32(acc[f], a, b2);
            }
        }
        __syncthreads();   // Hs reads done -> alias as Acc

        #pragma unroll
        for (int f = 0; f < 4; f++) {
            int col = n0 + f * 8 + 2 * tig;
            *(float2*)&Acc[(m0 + gid    ) * HS + col] = make_float2(acc[f][0], acc[f][1]);
            *(float2*)&Acc[(m0 + gid + 8) * HS + col] = make_float2(acc[f][2], acc[f][3]);
        }
        __syncthreads();

        // pointwise: thread owns (b=pb, units pu4..pu4+3)
        int nb = (step & 1) ^ 1;
        float hv[4];
        #pragma unroll
        for (int j = 0; j < 4; j++) {
            int u = pu4 + j;
            float gi = Acc[( 0 + u) * HS + pb] + XGs[( 0 + u) * 64 + pb];
            float gf = Acc[(16 + u) * HS + pb] + XGs[(16 + u) * 64 + pb];
            float gg = Acc[(32 + u) * HS + pb] + XGs[(32 + u) * 64 + pb];
            float go = Acc[(48 + u) * HS + pb] + XGs[(48 + u) * 64 + pb];
            float iv = sigm_f(gi);
            float fv = sigm_f(gf);
            float gv = tanh_f(gg);
            float ov = sigm_f(go);
            cst[j] = fv * cst[j] + iv * gv;
            hv[j] = ov * tanh_f(cst[j]);
        }
        float4 h4 = make_float4(hv[0], hv[1], hv[2], hv[3]);
        __stcg((float4*)&g_hst[nb][dir][b0 + pb][ug * 16 + pu4], h4);

        float4 o4 = h4;
        if (!to_ext) {   // layer-0 output feeds tf32 GEMM: pre-round
            o4.x = __uint_as_float(f2tf32(o4.x));
            o4.y = __uint_as_float(f2tf32(o4.y));
            o4.z = __uint_as_float(f2tf32(o4.z));
            o4.w = __uint_as_float(f2tf32(o4.w));
        }
        *(float4*)(out + ((size_t)t * B_ + b0 + pb) * 512 + dir * H_ + ug * 16 + pu4) = o4;

        __syncthreads();   // all XGs reads done
        if (step + 1 < T_) {   // prefetch next xg; overlaps the barrier
            int tn = dir ? (T_ - 1 - (step + 1)) : (step + 1);
            const float* xgt = xg + (size_t)tn * (G_ * B_);
            #pragma unroll
            for (int i = 0; i < 4; i++) {
                int c = tid + i * 256;
                int r = c >> 4, boff = (c & 15) * 4;
                int grow = (r >> 4) * H_ + ug * 16 + (r & 15);
                cp16(cvta_s(XGs + r * 64 + boff), xgt + (size_t)grow * B_ + b0 + boff);
            }
            CP_COMMIT();
        }
        group_barrier(grp);
    }
}

// ---------------- launch ----------------------------------------------------
extern "C" void kernel_launch(void* const* d_in, const int* in_sizes, int n_in,
                              void* d_out, int out_size) {
    const float* x     = (const float*)d_in[0];
    const float* wih0f = (const float*)d_in[1];
    const float* whh0f = (const float*)d_in[2];
    const float* bih0f = (const float*)d_in[3];
    const float* bhh0f = (const float*)d_in[4];
    const float* wih0b = (const float*)d_in[5];
    const float* whh0b = (const float*)d_in[6];
    const float* bih0b = (const float*)d_in[7];
    const float* bhh0b = (const float*)d_in[8];
    const float* wih1f = (const float*)d_in[9];
    const float* whh1f = (const float*)d_in[10];
    const float* bih1f = (const float*)d_in[11];
    const float* bhh1f = (const float*)d_in[12];
    const float* wih1b = (const float*)d_in[13];
    const float* whh1b = (const float*)d_in[14];
    const float* bih1b = (const float*)d_in[15];
    const float* bhh1b = (const float*)d_in[16];
    float* out = (float*)d_out;

    static int inited = 0;
    if (!inited) {
        cudaFuncSetAttribute(gemm_xg, cudaFuncAttributeMaxDynamicSharedMemorySize, GEMM_SMEM);
        cudaFuncSetAttribute(lstm_rec_mma, cudaFuncAttributeMaxDynamicSharedMemorySize, REC_SMEM);
        inited = 1;
    }

    prep_round<<<2048, 256>>>(x, wih0f, wih0b, wih1f, wih1b);

    dim3 gg(2, 16, T_);
    gemm_xg<<<gg, 256, GEMM_SMEM>>>(0, bih0f, bhh0f, bih0b, bhh0b);
    lstm_rec_mma<<<128, 256, REC_SMEM>>>(whh0f, whh0b, out, 0);
    gemm_xg<<<gg, 256, GEMM_SMEM>>>(1, bih1f, bhh1f, bih1b, bhh1b);
    lstm_rec_mma<<<128, 256, REC_SMEM>>>(whh1f, whh1b, out, 1);
}